// round 2
// baseline (speedup 1.0000x reference)
#include <cuda_runtime.h>
#include <cstdint>

// Problem constants (fixed by the dataset)
#define N_NODES 50000
#define N_FEAT  256
#define HIDDEN  256
#define H2      128
#define N_EDGES 800000

// ---------------------------------------------------------------------------
// Scratch (device globals — no cudaMalloc allowed)
// ---------------------------------------------------------------------------
__device__ float g_h1  [N_NODES * HIDDEN];  // x@W1, later reused for relu(agg1+b1)
__device__ float g_agg1[N_NODES * HIDDEN];  // layer-1 aggregation
__device__ float g_h2  [N_NODES * H2];      // h@W2
__device__ float g_z   [N_NODES * H2];      // layer-2 aggregation (+b2 in place)
__device__ float g_dinv[N_NODES];
__device__ int   g_deg [N_NODES];
__device__ int   g_tr  [2 * N_EDGES];       // converted int32 train edges
__device__ int   g_pe  [2 * N_EDGES];       // converted int32 pos edges
__device__ int   g_ne  [2 * N_EDGES];       // converted int32 neg edges
__device__ unsigned int g_or;               // dtype detection scratch
__device__ int   g_is64;                    // 1 if inputs are int64

// ---------------------------------------------------------------------------
// Index dtype detection: for int64 (non-negative) arrays every odd 32-bit word
// is zero; for int32 random indices the OR of odd words is nonzero.
// ---------------------------------------------------------------------------
__global__ void k_detect(const unsigned int* __restrict__ raw) {
    __shared__ unsigned int sh;
    if (threadIdx.x == 0) sh = 0u;
    __syncthreads();
    // sample 2048 odd words spread over the first 2*E words
    unsigned int acc = 0;
    for (int i = threadIdx.x; i < 2048; i += blockDim.x) {
        int idx = 2 * (i * 391) + 1;   // stride through elements
        acc |= raw[idx];
    }
    atomicOr(&sh, acc);
    __syncthreads();
    if (threadIdx.x == 0) g_is64 = (sh == 0u) ? 1 : 0;
}

__global__ void k_convert(const void* __restrict__ raw, int* __restrict__ out, int count) {
    int i = blockIdx.x * blockDim.x + threadIdx.x;
    if (i >= count) return;
    if (g_is64) out[i] = (int)((const long long*)raw)[i];
    else        out[i] = ((const int*)raw)[i];
}

// ---------------------------------------------------------------------------
// Vectorized global reduction (no return) — sm_90+: red.global.add.v4.f32
// ---------------------------------------------------------------------------
__device__ __forceinline__ void red_add_v4(float* addr, float x, float y, float z, float w) {
    asm volatile("red.global.add.v4.f32 [%0], {%1, %2, %3, %4};"
                 :: "l"(addr), "f"(x), "f"(y), "f"(z), "f"(w) : "memory");
}

// ---------------------------------------------------------------------------
// Degree / normalization
// ---------------------------------------------------------------------------
__global__ void k_deg_init(int* deg) {
    int i = blockIdx.x * blockDim.x + threadIdx.x;
    if (i < N_NODES) deg[i] = 1;  // self-loop
}

__global__ void k_deg_count(const int* __restrict__ tr, int* deg) {
    int e = blockIdx.x * blockDim.x + threadIdx.x;
    if (e < N_EDGES) {
        int d = tr[N_EDGES + e];  // dst row
        atomicAdd(&deg[d], 1);
    }
}

__global__ void k_dinv(const int* __restrict__ deg, float* dinv) {
    int i = blockIdx.x * blockDim.x + threadIdx.x;
    if (i < N_NODES) dinv[i] = rsqrtf((float)deg[i]);
}

// ---------------------------------------------------------------------------
// SGEMM: C[M,N] = A[M,K] @ B[K,N], row-major. BM=128 BN=128 BK=8 TM=TN=8, 256 thr
// ---------------------------------------------------------------------------
template <int BM, int BN, int BK, int TM, int TN>
__global__ __launch_bounds__(256) void sgemm(int M, int N, int K,
                                             const float* __restrict__ A,
                                             const float* __restrict__ B,
                                             float* __restrict__ C) {
    __shared__ float As[BK][BM];
    __shared__ float Bs[BK][BN];

    const int tid    = threadIdx.x;          // 0..255
    const int rowBlk = blockIdx.y * BM;
    const int colBlk = blockIdx.x * BN;

    const int tcol = (tid % (BN / TN)) * TN; // 16 cols of threads
    const int trow = (tid / (BN / TN)) * TM; // 16 rows of threads

    const int aRow  = tid / (BK / 4);        // 0..127
    const int aCol4 = (tid % (BK / 4)) * 4;  // 0 or 4
    const int bRow  = tid / (BN / 4);        // 0..7
    const int bCol4 = (tid % (BN / 4)) * 4;  // 0..124

    float acc[TM][TN];
#pragma unroll
    for (int m = 0; m < TM; m++)
#pragma unroll
        for (int n = 0; n < TN; n++) acc[m][n] = 0.f;

    for (int k0 = 0; k0 < K; k0 += BK) {
        float4 av = make_float4(0.f, 0.f, 0.f, 0.f);
        int gRow = rowBlk + aRow;
        if (gRow < M)
            av = *(const float4*)&A[(size_t)gRow * K + k0 + aCol4];
        As[aCol4 + 0][aRow] = av.x;
        As[aCol4 + 1][aRow] = av.y;
        As[aCol4 + 2][aRow] = av.z;
        As[aCol4 + 3][aRow] = av.w;

        float4 bv = *(const float4*)&B[(size_t)(k0 + bRow) * N + colBlk + bCol4];
        *(float4*)&Bs[bRow][bCol4] = bv;

        __syncthreads();
#pragma unroll
        for (int kk = 0; kk < BK; kk++) {
            float ra[TM], rb[TN];
#pragma unroll
            for (int m = 0; m < TM; m++) ra[m] = As[kk][trow + m];
#pragma unroll
            for (int n = 0; n < TN; n++) rb[n] = Bs[kk][tcol + n];
#pragma unroll
            for (int m = 0; m < TM; m++)
#pragma unroll
                for (int n = 0; n < TN; n++) acc[m][n] += ra[m] * rb[n];
        }
        __syncthreads();
    }

#pragma unroll
    for (int m = 0; m < TM; m++) {
        int gR = rowBlk + trow + m;
        if (gR < M) {
#pragma unroll
            for (int n = 0; n < TN; n += 4) {
                float4 v = make_float4(acc[m][n], acc[m][n + 1], acc[m][n + 2], acc[m][n + 3]);
                *(float4*)&C[(size_t)gR * N + colBlk + tcol + n] = v;
            }
        }
    }
}

// ---------------------------------------------------------------------------
// Aggregation
// ---------------------------------------------------------------------------
__global__ void k_agg_init(const float* __restrict__ h, const float* __restrict__ dinv,
                           float* __restrict__ agg, int C) {
    int idx = blockIdx.x * blockDim.x + threadIdx.x;  // over N*C/4
    int total = N_NODES * (C / 4);
    if (idx >= total) return;
    int node = idx / (C / 4);
    float s = dinv[node];
    s *= s;
    float4 v = ((const float4*)h)[idx];
    v.x *= s; v.y *= s; v.z *= s; v.w *= s;
    ((float4*)agg)[idx] = v;
}

__global__ void k_agg_edges(const int* __restrict__ tr,
                            const float* __restrict__ h,
                            const float* __restrict__ dinv,
                            float* __restrict__ agg, int C) {
    int gtid = blockIdx.x * blockDim.x + threadIdx.x;
    int warp = gtid >> 5;
    int lane = gtid & 31;
    if (warp >= N_EDGES) return;
    int s = tr[warp];
    int d = tr[N_EDGES + warp];
    float norm = dinv[s] * dinv[d];
    const float4* hs = (const float4*)&h[(size_t)s * C];
    float* ad = &agg[(size_t)d * C];
    for (int j = lane; j < C / 4; j += 32) {
        float4 v = hs[j];
        red_add_v4(&ad[j * 4], v.x * norm, v.y * norm, v.z * norm, v.w * norm);
    }
}

// h_out = relu(agg + b)
__global__ void k_relu_bias(const float* __restrict__ agg, const float* __restrict__ b,
                            float* __restrict__ h_out, int C) {
    int idx = blockIdx.x * blockDim.x + threadIdx.x;
    int total = N_NODES * (C / 4);
    if (idx >= total) return;
    int c4 = (idx % (C / 4)) * 4;
    float4 v = ((const float4*)agg)[idx];
    v.x = fmaxf(v.x + __ldg(&b[c4 + 0]), 0.f);
    v.y = fmaxf(v.y + __ldg(&b[c4 + 1]), 0.f);
    v.z = fmaxf(v.z + __ldg(&b[c4 + 2]), 0.f);
    v.w = fmaxf(v.w + __ldg(&b[c4 + 3]), 0.f);
    ((float4*)h_out)[idx] = v;
}

// z += b2 (in place)
__global__ void k_bias(float* __restrict__ z, const float* __restrict__ b, int C) {
    int idx = blockIdx.x * blockDim.x + threadIdx.x;
    int total = N_NODES * (C / 4);
    if (idx >= total) return;
    int c4 = (idx % (C / 4)) * 4;
    float4 v = ((float4*)z)[idx];
    v.x += __ldg(&b[c4 + 0]);
    v.y += __ldg(&b[c4 + 1]);
    v.z += __ldg(&b[c4 + 2]);
    v.w += __ldg(&b[c4 + 3]);
    ((float4*)z)[idx] = v;
}

// ---------------------------------------------------------------------------
// Decode: logits[e] = dot(z[a], z[b]), 128-dim, warp per edge.
// ---------------------------------------------------------------------------
__global__ void k_decode(const int* __restrict__ pe,
                         const int* __restrict__ ne,
                         const float* __restrict__ z,
                         float* __restrict__ out) {
    int gtid = blockIdx.x * blockDim.x + threadIdx.x;
    int warp = gtid >> 5;
    int lane = gtid & 31;
    if (warp >= 2 * N_EDGES) return;
    int a, b;
    if (warp < N_EDGES) {
        a = pe[warp];
        b = pe[N_EDGES + warp];
    } else {
        int e = warp - N_EDGES;
        a = ne[e];
        b = ne[N_EDGES + e];
    }
    float4 va = ((const float4*)&z[(size_t)a * H2])[lane];
    float4 vb = ((const float4*)&z[(size_t)b * H2])[lane];
    float s = va.x * vb.x + va.y * vb.y + va.z * vb.z + va.w * vb.w;
#pragma unroll
    for (int o = 16; o; o >>= 1) s += __shfl_xor_sync(0xFFFFFFFFu, s, o);
    if (lane == 0) out[warp] = s;
}

// ---------------------------------------------------------------------------
// Launch
// ---------------------------------------------------------------------------
extern "C" void kernel_launch(void* const* d_in, const int* in_sizes, int n_in,
                              void* d_out, int out_size) {
    const float* x    = (const float*)d_in[0];
    const void*  trR  = d_in[1];
    const void*  peR  = d_in[2];
    const void*  neR  = d_in[3];
    const float* W1   = (const float*)d_in[4];
    const float* b1   = (const float*)d_in[5];
    const float* W2   = (const float*)d_in[6];
    const float* b2   = (const float*)d_in[7];
    float* out = (float*)d_out;

    float *h1, *agg1, *h2, *z, *dinv;
    int *deg, *tr, *pe, *ne;
    cudaGetSymbolAddress((void**)&h1,   g_h1);
    cudaGetSymbolAddress((void**)&agg1, g_agg1);
    cudaGetSymbolAddress((void**)&h2,   g_h2);
    cudaGetSymbolAddress((void**)&z,    g_z);
    cudaGetSymbolAddress((void**)&dinv, g_dinv);
    cudaGetSymbolAddress((void**)&deg,  g_deg);
    cudaGetSymbolAddress((void**)&tr,   g_tr);
    cudaGetSymbolAddress((void**)&pe,   g_pe);
    cudaGetSymbolAddress((void**)&ne,   g_ne);

    const int EC = 2 * N_EDGES;

    // 0. detect index dtype and convert to int32
    k_detect<<<1, 256>>>((const unsigned int*)trR);
    k_convert<<<(EC + 255) / 256, 256>>>(trR, tr, EC);
    k_convert<<<(EC + 255) / 256, 256>>>(peR, pe, EC);
    k_convert<<<(EC + 255) / 256, 256>>>(neR, ne, EC);

    // 1. degree + normalization
    k_deg_init<<<(N_NODES + 255) / 256, 256>>>(deg);
    k_deg_count<<<(N_EDGES + 255) / 256, 256>>>(tr, deg);
    k_dinv<<<(N_NODES + 255) / 256, 256>>>(deg, dinv);

    // 2. h1 = x @ W1
    {
        dim3 grid(HIDDEN / 128, (N_NODES + 127) / 128);
        sgemm<128, 128, 8, 8, 8><<<grid, 256>>>(N_NODES, HIDDEN, N_FEAT, x, W1, h1);
    }

    // 3. layer-1 aggregation + relu + bias
    {
        int tot = N_NODES * (HIDDEN / 4);
        k_agg_init<<<(tot + 255) / 256, 256>>>(h1, dinv, agg1, HIDDEN);
        long long threads = (long long)N_EDGES * 32;
        k_agg_edges<<<(unsigned)((threads + 255) / 256), 256>>>(tr, h1, dinv, agg1, HIDDEN);
        k_relu_bias<<<(tot + 255) / 256, 256>>>(agg1, b1, h1, HIDDEN);  // h1 now = relu output
    }

    // 4. h2 = h1 @ W2
    {
        dim3 grid(H2 / 128, (N_NODES + 127) / 128);
        sgemm<128, 128, 8, 8, 8><<<grid, 256>>>(N_NODES, H2, HIDDEN, h1, W2, h2);
    }

    // 5. layer-2 aggregation + bias -> z
    {
        int tot = N_NODES * (H2 / 4);
        k_agg_init<<<(tot + 255) / 256, 256>>>(h2, dinv, z, H2);
        long long threads = (long long)N_EDGES * 32;
        k_agg_edges<<<(unsigned)((threads + 255) / 256), 256>>>(tr, h2, dinv, z, H2);
        k_bias<<<(tot + 255) / 256, 256>>>(z, b2, H2);
    }

    // 6. decode
    {
        long long threads = (long long)2 * N_EDGES * 32;
        k_decode<<<(unsigned)((threads + 255) / 256), 256>>>(pe, ne, z, out);
    }
}

// round 3
// speedup vs baseline: 1.2954x; 1.2954x over previous
#include <cuda_runtime.h>
#include <cstdint>

// Problem constants (fixed by the dataset)
#define N_NODES 50000
#define N_FEAT  256
#define HIDDEN  256
#define H2      128
#define N_EDGES 800000

// ---------------------------------------------------------------------------
// Scratch (device globals — no cudaMalloc allowed)
// ---------------------------------------------------------------------------
__device__ float g_h1  [N_NODES * HIDDEN];  // x@W1, later reused for relu(agg1+b1)
__device__ float g_agg1[N_NODES * HIDDEN];  // layer-1 aggregation
__device__ float g_h2  [N_NODES * H2];      // h@W2
__device__ float g_z   [N_NODES * H2];      // layer-2 aggregation (+b2 in place)
__device__ float g_dinv[N_NODES];
__device__ int   g_deg [N_NODES];
__device__ int   g_tr  [2 * N_EDGES];       // converted int32 train edges
__device__ int   g_is64;                    // 1 if int index inputs are int64

// ---------------------------------------------------------------------------
// Index dtype detection: for int64 (non-negative) arrays every odd 32-bit word
// is zero; for int32 random indices the OR of odd words is nonzero.
// ---------------------------------------------------------------------------
__global__ void k_detect(const unsigned int* __restrict__ raw) {
    __shared__ unsigned int sh;
    if (threadIdx.x == 0) sh = 0u;
    __syncthreads();
    unsigned int acc = 0;
    for (int i = threadIdx.x; i < 2048; i += blockDim.x) {
        int idx = 2 * (i * 391) + 1;
        acc |= raw[idx];
    }
    atomicOr(&sh, acc);
    __syncthreads();
    if (threadIdx.x == 0) g_is64 = (sh == 0u) ? 1 : 0;
}

__global__ void k_convert(const void* __restrict__ raw, int* __restrict__ out, int count) {
    int i = blockIdx.x * blockDim.x + threadIdx.x;
    if (i >= count) return;
    if (g_is64) out[i] = (int)((const long long*)raw)[i];
    else        out[i] = ((const int*)raw)[i];
}

// ---------------------------------------------------------------------------
// Vectorized global reduction (no return) — sm_90+: red.global.add.v4.f32
// ---------------------------------------------------------------------------
__device__ __forceinline__ void red_add_v4(float* addr, float x, float y, float z, float w) {
    asm volatile("red.global.add.v4.f32 [%0], {%1, %2, %3, %4};"
                 :: "l"(addr), "f"(x), "f"(y), "f"(z), "f"(w) : "memory");
}

// ---------------------------------------------------------------------------
// Degree / normalization
// ---------------------------------------------------------------------------
__global__ void k_deg_init(int* deg) {
    int i = blockIdx.x * blockDim.x + threadIdx.x;
    if (i < N_NODES) deg[i] = 1;  // self-loop
}

__global__ void k_deg_count(const int* __restrict__ tr, int* deg) {
    int e = blockIdx.x * blockDim.x + threadIdx.x;
    if (e < N_EDGES) atomicAdd(&deg[tr[N_EDGES + e]], 1);
}

__global__ void k_dinv(const int* __restrict__ deg, float* dinv) {
    int i = blockIdx.x * blockDim.x + threadIdx.x;
    if (i < N_NODES) dinv[i] = rsqrtf((float)deg[i]);
}

// ---------------------------------------------------------------------------
// TF32 tensor-core GEMM: C[M,N] = A[M,K] @ B[K,N], row-major.
// BM=128 BN=128 BK=16, 256 threads (8 warps as 2(m)x4(n)), warp tile 64x32,
// mma.sync.aligned.m16n8k8.row.col.f32.tf32.tf32.f32.
// Smem stride 136 floats -> fragment LDS bank = (8*tig + groupID) % 32,
// conflict-free. Inputs rounded to tf32 with cvt.rna at smem-store time.
// ---------------------------------------------------------------------------
#define GBM 128
#define GBN 128
#define GBK 16
#define SSTR 136   // GBM + 8 padding

__device__ __forceinline__ uint32_t f2tf32(float f) {
    uint32_t r;
    asm("cvt.rna.tf32.f32 %0, %1;" : "=r"(r) : "f"(f));
    return r;
}

__device__ __forceinline__ void mma_tf32(float* c, const uint32_t* a, const uint32_t* b) {
    asm volatile(
        "mma.sync.aligned.m16n8k8.row.col.f32.tf32.tf32.f32 "
        "{%0,%1,%2,%3}, {%4,%5,%6,%7}, {%8,%9}, {%0,%1,%2,%3};"
        : "+f"(c[0]), "+f"(c[1]), "+f"(c[2]), "+f"(c[3])
        : "r"(a[0]), "r"(a[1]), "r"(a[2]), "r"(a[3]), "r"(b[0]), "r"(b[1]));
}

__global__ __launch_bounds__(256) void gemm_tf32(int M, int N, int K,
                                                 const float* __restrict__ A,
                                                 const float* __restrict__ B,
                                                 float* __restrict__ C) {
    __shared__ float As[GBK][SSTR];   // As[k][m]
    __shared__ float Bs[GBK][SSTR];   // Bs[k][n]

    const int tid  = threadIdx.x;
    const int wid  = tid >> 5;
    const int lane = tid & 31;
    const int grp  = lane >> 2;   // groupID 0..7
    const int tig  = lane & 3;    // threadID_in_group 0..3

    const int warp_m = wid & 1;   // 0..1  -> 64 rows each
    const int warp_n = wid >> 1;  // 0..3  -> 32 cols each
    const int wrow = warp_m * 64;
    const int wcol = warp_n * 32;

    const int rowBlk = blockIdx.y * GBM;
    const int colBlk = blockIdx.x * GBN;

    // Global loaders
    const int aRow  = tid >> 2;          // 0..63, +64 on second pass
    const int aCol4 = (tid & 3) * 4;     // 0,4,8,12
    const int bRowL = tid >> 5;          // 0..7, +8 on second pass
    const int bCol4 = (tid & 31) * 4;    // 0..124

    float acc[4][4][4];
#pragma unroll
    for (int i = 0; i < 4; i++)
#pragma unroll
        for (int j = 0; j < 4; j++)
#pragma unroll
            for (int t = 0; t < 4; t++) acc[i][j][t] = 0.f;

    for (int k0 = 0; k0 < K; k0 += GBK) {
        // Load A tile (128 x 16), store transposed as As[k][m] with tf32 rounding
#pragma unroll
        for (int r = 0; r < 2; r++) {
            int gr = rowBlk + aRow + r * 64;
            float4 v = make_float4(0.f, 0.f, 0.f, 0.f);
            if (gr < M) v = *(const float4*)&A[(size_t)gr * K + k0 + aCol4];
            int m = aRow + r * 64;
            As[aCol4 + 0][m] = __uint_as_float(f2tf32(v.x));
            As[aCol4 + 1][m] = __uint_as_float(f2tf32(v.y));
            As[aCol4 + 2][m] = __uint_as_float(f2tf32(v.z));
            As[aCol4 + 3][m] = __uint_as_float(f2tf32(v.w));
        }
        // Load B tile (16 x 128), natural layout Bs[k][n], tf32-rounded, float4 store
#pragma unroll
        for (int r = 0; r < 2; r++) {
            int gk = k0 + bRowL + r * 8;
            float4 v = *(const float4*)&B[(size_t)gk * N + colBlk + bCol4];
            float4 t;
            t.x = __uint_as_float(f2tf32(v.x));
            t.y = __uint_as_float(f2tf32(v.y));
            t.z = __uint_as_float(f2tf32(v.z));
            t.w = __uint_as_float(f2tf32(v.w));
            *(float4*)&Bs[bRowL + r * 8][bCol4] = t;
        }
        __syncthreads();

#pragma unroll
        for (int ks = 0; ks < GBK; ks += 8) {
            uint32_t afr[4][4];
            uint32_t bfr[4][2];
#pragma unroll
            for (int i = 0; i < 4; i++) {
                int r = wrow + i * 16;
                afr[i][0] = __float_as_uint(As[ks + tig    ][r + grp    ]);
                afr[i][1] = __float_as_uint(As[ks + tig    ][r + grp + 8]);
                afr[i][2] = __float_as_uint(As[ks + tig + 4][r + grp    ]);
                afr[i][3] = __float_as_uint(As[ks + tig + 4][r + grp + 8]);
            }
#pragma unroll
            for (int j = 0; j < 4; j++) {
                int c = wcol + j * 8;
                bfr[j][0] = __float_as_uint(Bs[ks + tig    ][c + grp]);
                bfr[j][1] = __float_as_uint(Bs[ks + tig + 4][c + grp]);
            }
#pragma unroll
            for (int i = 0; i < 4; i++)
#pragma unroll
                for (int j = 0; j < 4; j++)
                    mma_tf32(acc[i][j], afr[i], bfr[j]);
        }
        __syncthreads();
    }

    // Store C: c0,c1 at (grp, 2*tig / 2*tig+1); c2,c3 at (grp+8, ...)
#pragma unroll
    for (int i = 0; i < 4; i++) {
        int r0 = rowBlk + wrow + i * 16 + grp;
#pragma unroll
        for (int j = 0; j < 4; j++) {
            int c = colBlk + wcol + j * 8 + 2 * tig;
            if (r0 < M)
                *(float2*)&C[(size_t)r0 * N + c] = make_float2(acc[i][j][0], acc[i][j][1]);
            if (r0 + 8 < M)
                *(float2*)&C[(size_t)(r0 + 8) * N + c] = make_float2(acc[i][j][2], acc[i][j][3]);
        }
    }
}

// ---------------------------------------------------------------------------
// Aggregation
// ---------------------------------------------------------------------------
__global__ void k_agg_init(const float* __restrict__ h, const float* __restrict__ dinv,
                           float* __restrict__ agg, int C) {
    int idx = blockIdx.x * blockDim.x + threadIdx.x;
    int total = N_NODES * (C / 4);
    if (idx >= total) return;
    int node = idx / (C / 4);
    float s = dinv[node];
    s *= s;
    float4 v = ((const float4*)h)[idx];
    v.x *= s; v.y *= s; v.z *= s; v.w *= s;
    ((float4*)agg)[idx] = v;
}

__global__ void k_agg_edges(const int* __restrict__ tr,
                            const float* __restrict__ h,
                            const float* __restrict__ dinv,
                            float* __restrict__ agg, int C) {
    int gtid = blockIdx.x * blockDim.x + threadIdx.x;
    int warp = gtid >> 5;
    int lane = gtid & 31;
    if (warp >= N_EDGES) return;
    int s = tr[warp];
    int d = tr[N_EDGES + warp];
    float norm = dinv[s] * dinv[d];
    const float4* hs = (const float4*)&h[(size_t)s * C];
    float* ad = &agg[(size_t)d * C];
    for (int j = lane; j < C / 4; j += 32) {
        float4 v = hs[j];
        red_add_v4(&ad[j * 4], v.x * norm, v.y * norm, v.z * norm, v.w * norm);
    }
}

// h_out = relu(agg + b)
__global__ void k_relu_bias(const float* __restrict__ agg, const float* __restrict__ b,
                            float* __restrict__ h_out, int C) {
    int idx = blockIdx.x * blockDim.x + threadIdx.x;
    int total = N_NODES * (C / 4);
    if (idx >= total) return;
    int c4 = (idx % (C / 4)) * 4;
    float4 v = ((const float4*)agg)[idx];
    v.x = fmaxf(v.x + __ldg(&b[c4 + 0]), 0.f);
    v.y = fmaxf(v.y + __ldg(&b[c4 + 1]), 0.f);
    v.z = fmaxf(v.z + __ldg(&b[c4 + 2]), 0.f);
    v.w = fmaxf(v.w + __ldg(&b[c4 + 3]), 0.f);
    ((float4*)h_out)[idx] = v;
}

// z += b2 (in place)
__global__ void k_bias(float* __restrict__ z, const float* __restrict__ b, int C) {
    int idx = blockIdx.x * blockDim.x + threadIdx.x;
    int total = N_NODES * (C / 4);
    if (idx >= total) return;
    int c4 = (idx % (C / 4)) * 4;
    float4 v = ((float4*)z)[idx];
    v.x += __ldg(&b[c4 + 0]);
    v.y += __ldg(&b[c4 + 1]);
    v.z += __ldg(&b[c4 + 2]);
    v.w += __ldg(&b[c4 + 3]);
    ((float4*)z)[idx] = v;
}

// ---------------------------------------------------------------------------
// Decode: logits[e] = dot(z[a], z[b]), 128-dim, warp per edge.
// Reads raw index arrays (int32 or int64 per g_is64) directly.
// ---------------------------------------------------------------------------
__global__ void k_decode(const void* __restrict__ peR,
                         const void* __restrict__ neR,
                         const float* __restrict__ z,
                         float* __restrict__ out) {
    int gtid = blockIdx.x * blockDim.x + threadIdx.x;
    int warp = gtid >> 5;
    int lane = gtid & 31;
    if (warp >= 2 * N_EDGES) return;
    const void* src = (warp < N_EDGES) ? peR : neR;
    int e = (warp < N_EDGES) ? warp : warp - N_EDGES;
    int a, b;
    if (g_is64) {
        a = (int)((const long long*)src)[e];
        b = (int)((const long long*)src)[N_EDGES + e];
    } else {
        a = ((const int*)src)[e];
        b = ((const int*)src)[N_EDGES + e];
    }
    float4 va = ((const float4*)&z[(size_t)a * H2])[lane];
    float4 vb = ((const float4*)&z[(size_t)b * H2])[lane];
    float s = va.x * vb.x + va.y * vb.y + va.z * vb.z + va.w * vb.w;
#pragma unroll
    for (int o = 16; o; o >>= 1) s += __shfl_xor_sync(0xFFFFFFFFu, s, o);
    if (lane == 0) out[warp] = s;
}

// ---------------------------------------------------------------------------
// Launch
// ---------------------------------------------------------------------------
extern "C" void kernel_launch(void* const* d_in, const int* in_sizes, int n_in,
                              void* d_out, int out_size) {
    const float* x    = (const float*)d_in[0];
    const void*  trR  = d_in[1];
    const void*  peR  = d_in[2];
    const void*  neR  = d_in[3];
    const float* W1   = (const float*)d_in[4];
    const float* b1   = (const float*)d_in[5];
    const float* W2   = (const float*)d_in[6];
    const float* b2   = (const float*)d_in[7];
    float* out = (float*)d_out;

    float *h1, *agg1, *h2, *z, *dinv;
    int *deg, *tr;
    cudaGetSymbolAddress((void**)&h1,   g_h1);
    cudaGetSymbolAddress((void**)&agg1, g_agg1);
    cudaGetSymbolAddress((void**)&h2,   g_h2);
    cudaGetSymbolAddress((void**)&z,    g_z);
    cudaGetSymbolAddress((void**)&dinv, g_dinv);
    cudaGetSymbolAddress((void**)&deg,  g_deg);
    cudaGetSymbolAddress((void**)&tr,   g_tr);

    const int EC = 2 * N_EDGES;

    // 0. detect index dtype; convert train edges (read 3x downstream)
    k_detect<<<1, 256>>>((const unsigned int*)trR);
    k_convert<<<(EC + 255) / 256, 256>>>(trR, tr, EC);

    // 1. degree + normalization
    k_deg_init<<<(N_NODES + 255) / 256, 256>>>(deg);
    k_deg_count<<<(N_EDGES + 255) / 256, 256>>>(tr, deg);
    k_dinv<<<(N_NODES + 255) / 256, 256>>>(deg, dinv);

    // 2. h1 = x @ W1   (tf32 tensor cores)
    {
        dim3 grid(HIDDEN / GBN, (N_NODES + GBM - 1) / GBM);
        gemm_tf32<<<grid, 256>>>(N_NODES, HIDDEN, N_FEAT, x, W1, h1);
    }

    // 3. layer-1 aggregation + relu + bias
    {
        int tot = N_NODES * (HIDDEN / 4);
        k_agg_init<<<(tot + 255) / 256, 256>>>(h1, dinv, agg1, HIDDEN);
        long long threads = (long long)N_EDGES * 32;
        k_agg_edges<<<(unsigned)((threads + 255) / 256), 256>>>(tr, h1, dinv, agg1, HIDDEN);
        k_relu_bias<<<(tot + 255) / 256, 256>>>(agg1, b1, h1, HIDDEN);  // h1 = relu output
    }

    // 4. h2 = h1 @ W2
    {
        dim3 grid(H2 / GBN, (N_NODES + GBM - 1) / GBM);
        gemm_tf32<<<grid, 256>>>(N_NODES, H2, HIDDEN, h1, W2, h2);
    }

    // 5. layer-2 aggregation + bias -> z
    {
        int tot = N_NODES * (H2 / 4);
        k_agg_init<<<(tot + 255) / 256, 256>>>(h2, dinv, z, H2);
        long long threads = (long long)N_EDGES * 32;
        k_agg_edges<<<(unsigned)((threads + 255) / 256), 256>>>(tr, h2, dinv, z, H2);
        k_bias<<<(tot + 255) / 256, 256>>>(z, b2, H2);
    }

    // 6. decode
    {
        long long threads = (long long)2 * N_EDGES * 32;
        k_decode<<<(unsigned)((threads + 255) / 256), 256>>>(peR, neR, z, out);
    }
}

// round 4
// speedup vs baseline: 1.7477x; 1.3492x over previous
#include <cuda_runtime.h>
#include <cstdint>

// Problem constants (fixed by the dataset)
#define N_NODES 50000
#define N_FEAT  256
#define HIDDEN  256
#define H2      128
#define N_EDGES 800000

// ---------------------------------------------------------------------------
// Scratch (device globals — no cudaMalloc allowed)
// ---------------------------------------------------------------------------
__device__ float g_h1  [N_NODES * HIDDEN];  // x@W1
__device__ float g_o1  [N_NODES * HIDDEN];  // relu(agg1 + b1)
__device__ float g_h2  [N_NODES * H2];      // o1@W2
__device__ float g_z   [N_NODES * H2];      // agg2 + b2
__device__ float g_dinv[N_NODES];
__device__ int   g_deg [N_NODES];           // 1 + in-degree
__device__ int   g_tr  [2 * N_EDGES];       // converted int32 train edges
__device__ int   g_rowptr[N_NODES + 1];     // CSR row offsets (by dst)
__device__ int   g_cursor[N_NODES];         // scatter cursors
__device__ int   g_csrc  [N_EDGES];         // CSR src indices
__device__ int   g_is64;                    // 1 if index inputs are int64

// ---------------------------------------------------------------------------
// Index dtype detection: for int64 (non-negative) arrays every odd 32-bit word
// is zero; for int32 random indices the OR of odd words is nonzero.
// ---------------------------------------------------------------------------
__global__ void k_detect(const unsigned int* __restrict__ raw) {
    __shared__ unsigned int sh;
    if (threadIdx.x == 0) sh = 0u;
    __syncthreads();
    unsigned int acc = 0;
    for (int i = threadIdx.x; i < 2048; i += blockDim.x) {
        int idx = 2 * (i * 391) + 1;
        acc |= raw[idx];
    }
    atomicOr(&sh, acc);
    __syncthreads();
    if (threadIdx.x == 0) g_is64 = (sh == 0u) ? 1 : 0;
}

__global__ void k_deg_init(int* deg) {
    int i = blockIdx.x * blockDim.x + threadIdx.x;
    if (i < N_NODES) deg[i] = 1;  // self-loop
}

// Convert train edges to int32 AND histogram dst degrees in the same pass.
__global__ void k_convert_tr(const void* __restrict__ raw, int* __restrict__ out,
                             int* __restrict__ deg) {
    int i = blockIdx.x * blockDim.x + threadIdx.x;
    if (i >= 2 * N_EDGES) return;
    int v;
    if (g_is64) v = (int)((const long long*)raw)[i];
    else        v = ((const int*)raw)[i];
    out[i] = v;
    if (i >= N_EDGES) atomicAdd(&deg[v], 1);   // dst half
}

__global__ void k_dinv(const int* __restrict__ deg, float* dinv) {
    int i = blockIdx.x * blockDim.x + threadIdx.x;
    if (i < N_NODES) dinv[i] = rsqrtf((float)deg[i]);
}

// ---------------------------------------------------------------------------
// One-block exclusive prefix scan over per-node edge counts (deg-1).
// ---------------------------------------------------------------------------
#define SCAN_T 1024
__global__ __launch_bounds__(SCAN_T) void k_scan(const int* __restrict__ deg,
                                                 int* __restrict__ rowptr,
                                                 int* __restrict__ cursor) {
    __shared__ int part[SCAN_T];
    int t = threadIdx.x;
    const int CH = (N_NODES + SCAN_T - 1) / SCAN_T;
    int base = t * CH;
    int s = 0;
    for (int i = 0; i < CH; i++) {
        int idx = base + i;
        if (idx < N_NODES) s += deg[idx] - 1;
    }
    part[t] = s;
    __syncthreads();
    for (int o = 1; o < SCAN_T; o <<= 1) {
        int v = (t >= o) ? part[t - o] : 0;
        __syncthreads();
        part[t] += v;
        __syncthreads();
    }
    int run = part[t] - s;  // exclusive chunk base
    for (int i = 0; i < CH; i++) {
        int idx = base + i;
        if (idx < N_NODES) {
            rowptr[idx] = run;
            cursor[idx] = run;
            run += deg[idx] - 1;
        }
    }
    if (t == SCAN_T - 1) rowptr[N_NODES] = run;
}

__global__ void k_scatter(const int* __restrict__ tr, int* __restrict__ cursor,
                          int* __restrict__ csrc) {
    int e = blockIdx.x * blockDim.x + threadIdx.x;
    if (e >= N_EDGES) return;
    int s = tr[e];
    int d = tr[N_EDGES + e];
    int pos = atomicAdd(&cursor[d], 1);
    csrc[pos] = s;
}

// ---------------------------------------------------------------------------
// TF32 tensor-core GEMM (unchanged from R3): BM=BN=128 BK=16, 256 threads.
// ---------------------------------------------------------------------------
#define GBM 128
#define GBN 128
#define GBK 16
#define SSTR 136

__device__ __forceinline__ uint32_t f2tf32(float f) {
    uint32_t r;
    asm("cvt.rna.tf32.f32 %0, %1;" : "=r"(r) : "f"(f));
    return r;
}

__device__ __forceinline__ void mma_tf32(float* c, const uint32_t* a, const uint32_t* b) {
    asm volatile(
        "mma.sync.aligned.m16n8k8.row.col.f32.tf32.tf32.f32 "
        "{%0,%1,%2,%3}, {%4,%5,%6,%7}, {%8,%9}, {%0,%1,%2,%3};"
        : "+f"(c[0]), "+f"(c[1]), "+f"(c[2]), "+f"(c[3])
        : "r"(a[0]), "r"(a[1]), "r"(a[2]), "r"(a[3]), "r"(b[0]), "r"(b[1]));
}

__global__ __launch_bounds__(256) void gemm_tf32(int M, int N, int K,
                                                 const float* __restrict__ A,
                                                 const float* __restrict__ B,
                                                 float* __restrict__ C) {
    __shared__ float As[GBK][SSTR];
    __shared__ float Bs[GBK][SSTR];

    const int tid  = threadIdx.x;
    const int wid  = tid >> 5;
    const int lane = tid & 31;
    const int grp  = lane >> 2;
    const int tig  = lane & 3;

    const int wrow = (wid & 1) * 64;
    const int wcol = (wid >> 1) * 32;

    const int rowBlk = blockIdx.y * GBM;
    const int colBlk = blockIdx.x * GBN;

    const int aRow  = tid >> 2;
    const int aCol4 = (tid & 3) * 4;
    const int bRowL = tid >> 5;
    const int bCol4 = (tid & 31) * 4;

    float acc[4][4][4];
#pragma unroll
    for (int i = 0; i < 4; i++)
#pragma unroll
        for (int j = 0; j < 4; j++)
#pragma unroll
            for (int t = 0; t < 4; t++) acc[i][j][t] = 0.f;

    for (int k0 = 0; k0 < K; k0 += GBK) {
#pragma unroll
        for (int r = 0; r < 2; r++) {
            int gr = rowBlk + aRow + r * 64;
            float4 v = make_float4(0.f, 0.f, 0.f, 0.f);
            if (gr < M) v = *(const float4*)&A[(size_t)gr * K + k0 + aCol4];
            int m = aRow + r * 64;
            As[aCol4 + 0][m] = __uint_as_float(f2tf32(v.x));
            As[aCol4 + 1][m] = __uint_as_float(f2tf32(v.y));
            As[aCol4 + 2][m] = __uint_as_float(f2tf32(v.z));
            As[aCol4 + 3][m] = __uint_as_float(f2tf32(v.w));
        }
#pragma unroll
        for (int r = 0; r < 2; r++) {
            int gk = k0 + bRowL + r * 8;
            float4 v = *(const float4*)&B[(size_t)gk * N + colBlk + bCol4];
            float4 t;
            t.x = __uint_as_float(f2tf32(v.x));
            t.y = __uint_as_float(f2tf32(v.y));
            t.z = __uint_as_float(f2tf32(v.z));
            t.w = __uint_as_float(f2tf32(v.w));
            *(float4*)&Bs[bRowL + r * 8][bCol4] = t;
        }
        __syncthreads();

#pragma unroll
        for (int ks = 0; ks < GBK; ks += 8) {
            uint32_t afr[4][4];
            uint32_t bfr[4][2];
#pragma unroll
            for (int i = 0; i < 4; i++) {
                int r = wrow + i * 16;
                afr[i][0] = __float_as_uint(As[ks + tig    ][r + grp    ]);
                afr[i][1] = __float_as_uint(As[ks + tig    ][r + grp + 8]);
                afr[i][2] = __float_as_uint(As[ks + tig + 4][r + grp    ]);
                afr[i][3] = __float_as_uint(As[ks + tig + 4][r + grp + 8]);
            }
#pragma unroll
            for (int j = 0; j < 4; j++) {
                int c = wcol + j * 8;
                bfr[j][0] = __float_as_uint(Bs[ks + tig    ][c + grp]);
                bfr[j][1] = __float_as_uint(Bs[ks + tig + 4][c + grp]);
            }
#pragma unroll
            for (int i = 0; i < 4; i++)
#pragma unroll
                for (int j = 0; j < 4; j++)
                    mma_tf32(acc[i][j], afr[i], bfr[j]);
        }
        __syncthreads();
    }

#pragma unroll
    for (int i = 0; i < 4; i++) {
        int r0 = rowBlk + wrow + i * 16 + grp;
#pragma unroll
        for (int j = 0; j < 4; j++) {
            int c = colBlk + wcol + j * 8 + 2 * tig;
            if (r0 < M)
                *(float2*)&C[(size_t)r0 * N + c] = make_float2(acc[i][j][0], acc[i][j][1]);
            if (r0 + 8 < M)
                *(float2*)&C[(size_t)(r0 + 8) * N + c] = make_float2(acc[i][j][2], acc[i][j][3]);
        }
    }
}

// ---------------------------------------------------------------------------
// CSR aggregation, warp per node, fused norm + bias (+ relu).
//   out[d] = act( sum_{s in N(d)} h[s]*dinv[s]*dinv[d] + h[d]*dinv[d]^2 + b )
// C floats per row; each lane holds C/128 float4 accumulators.
// ---------------------------------------------------------------------------
template <int C, bool RELU>
__global__ __launch_bounds__(256) void k_agg_csr(const int* __restrict__ rowptr,
                                                 const int* __restrict__ csrc,
                                                 const float* __restrict__ h,
                                                 const float* __restrict__ dinv,
                                                 const float* __restrict__ bias,
                                                 float* __restrict__ out) {
    constexpr int V = C / 128;  // float4 per lane (2 for C=256, 1 for C=128)
    int gtid = blockIdx.x * blockDim.x + threadIdx.x;
    int node = gtid >> 5;
    int lane = gtid & 31;
    if (node >= N_NODES) return;

    float di = dinv[node];
    float4 acc[V];
    const float4* hd = (const float4*)&h[(size_t)node * C];
    float self = di * di;
#pragma unroll
    for (int v = 0; v < V; v++) {
        float4 t = __ldg(&hd[lane + 32 * v]);
        acc[v].x = t.x * self; acc[v].y = t.y * self;
        acc[v].z = t.z * self; acc[v].w = t.w * self;
    }

    int beg = rowptr[node];
    int end = rowptr[node + 1];
    int p = beg;
    // unrolled by 2 for MLP
    for (; p + 2 <= end; p += 2) {
        int s0 = __ldg(&csrc[p]);
        int s1 = __ldg(&csrc[p + 1]);
        float n0 = di * __ldg(&dinv[s0]);
        float n1 = di * __ldg(&dinv[s1]);
        const float4* r0 = (const float4*)&h[(size_t)s0 * C];
        const float4* r1 = (const float4*)&h[(size_t)s1 * C];
#pragma unroll
        for (int v = 0; v < V; v++) {
            float4 a = __ldg(&r0[lane + 32 * v]);
            float4 b = __ldg(&r1[lane + 32 * v]);
            acc[v].x += a.x * n0 + b.x * n1;
            acc[v].y += a.y * n0 + b.y * n1;
            acc[v].z += a.z * n0 + b.z * n1;
            acc[v].w += a.w * n0 + b.w * n1;
        }
    }
    if (p < end) {
        int s0 = __ldg(&csrc[p]);
        float n0 = di * __ldg(&dinv[s0]);
        const float4* r0 = (const float4*)&h[(size_t)s0 * C];
#pragma unroll
        for (int v = 0; v < V; v++) {
            float4 a = __ldg(&r0[lane + 32 * v]);
            acc[v].x += a.x * n0; acc[v].y += a.y * n0;
            acc[v].z += a.z * n0; acc[v].w += a.w * n0;
        }
    }

    float4* od = (float4*)&out[(size_t)node * C];
#pragma unroll
    for (int v = 0; v < V; v++) {
        int c = (lane + 32 * v) * 4;
        acc[v].x += __ldg(&bias[c + 0]);
        acc[v].y += __ldg(&bias[c + 1]);
        acc[v].z += __ldg(&bias[c + 2]);
        acc[v].w += __ldg(&bias[c + 3]);
        if (RELU) {
            acc[v].x = fmaxf(acc[v].x, 0.f);
            acc[v].y = fmaxf(acc[v].y, 0.f);
            acc[v].z = fmaxf(acc[v].z, 0.f);
            acc[v].w = fmaxf(acc[v].w, 0.f);
        }
        od[lane + 32 * v] = acc[v];
    }
}

// ---------------------------------------------------------------------------
// Decode: logits[e] = dot(z[a], z[b]), 128-dim, warp per edge.
// ---------------------------------------------------------------------------
__global__ void k_decode(const void* __restrict__ peR,
                         const void* __restrict__ neR,
                         const float* __restrict__ z,
                         float* __restrict__ out) {
    int gtid = blockIdx.x * blockDim.x + threadIdx.x;
    int warp = gtid >> 5;
    int lane = gtid & 31;
    if (warp >= 2 * N_EDGES) return;
    const void* src = (warp < N_EDGES) ? peR : neR;
    int e = (warp < N_EDGES) ? warp : warp - N_EDGES;
    int a, b;
    if (g_is64) {
        a = (int)((const long long*)src)[e];
        b = (int)((const long long*)src)[N_EDGES + e];
    } else {
        a = ((const int*)src)[e];
        b = ((const int*)src)[N_EDGES + e];
    }
    float4 va = __ldg(&((const float4*)&z[(size_t)a * H2])[lane]);
    float4 vb = __ldg(&((const float4*)&z[(size_t)b * H2])[lane]);
    float s = va.x * vb.x + va.y * vb.y + va.z * vb.z + va.w * vb.w;
#pragma unroll
    for (int o = 16; o; o >>= 1) s += __shfl_xor_sync(0xFFFFFFFFu, s, o);
    if (lane == 0) out[warp] = s;
}

// ---------------------------------------------------------------------------
// Launch
// ---------------------------------------------------------------------------
extern "C" void kernel_launch(void* const* d_in, const int* in_sizes, int n_in,
                              void* d_out, int out_size) {
    const float* x    = (const float*)d_in[0];
    const void*  trR  = d_in[1];
    const void*  peR  = d_in[2];
    const void*  neR  = d_in[3];
    const float* W1   = (const float*)d_in[4];
    const float* b1   = (const float*)d_in[5];
    const float* W2   = (const float*)d_in[6];
    const float* b2   = (const float*)d_in[7];
    float* out = (float*)d_out;

    float *h1, *o1, *h2, *z, *dinv;
    int *deg, *tr, *rowptr, *cursor, *csrc;
    cudaGetSymbolAddress((void**)&h1,     g_h1);
    cudaGetSymbolAddress((void**)&o1,     g_o1);
    cudaGetSymbolAddress((void**)&h2,     g_h2);
    cudaGetSymbolAddress((void**)&z,      g_z);
    cudaGetSymbolAddress((void**)&dinv,   g_dinv);
    cudaGetSymbolAddress((void**)&deg,    g_deg);
    cudaGetSymbolAddress((void**)&tr,     g_tr);
    cudaGetSymbolAddress((void**)&rowptr, g_rowptr);
    cudaGetSymbolAddress((void**)&cursor, g_cursor);
    cudaGetSymbolAddress((void**)&csrc,   g_csrc);

    const int EC = 2 * N_EDGES;

    // 0. dtype detect, deg init, convert+histogram, dinv
    k_detect<<<1, 256>>>((const unsigned int*)trR);
    k_deg_init<<<(N_NODES + 255) / 256, 256>>>(deg);
    k_convert_tr<<<(EC + 255) / 256, 256>>>(trR, tr, deg);
    k_dinv<<<(N_NODES + 255) / 256, 256>>>(deg, dinv);

    // 1. CSR build
    k_scan<<<1, SCAN_T>>>(deg, rowptr, cursor);
    k_scatter<<<(N_EDGES + 255) / 256, 256>>>(tr, cursor, csrc);

    // 2. h1 = x @ W1
    {
        dim3 grid(HIDDEN / GBN, (N_NODES + GBM - 1) / GBM);
        gemm_tf32<<<grid, 256>>>(N_NODES, HIDDEN, N_FEAT, x, W1, h1);
    }

    // 3. o1 = relu(agg(h1) + b1)
    {
        long long threads = (long long)N_NODES * 32;
        k_agg_csr<HIDDEN, true><<<(unsigned)((threads + 255) / 256), 256>>>(
            rowptr, csrc, h1, dinv, b1, o1);
    }

    // 4. h2 = o1 @ W2
    {
        dim3 grid(H2 / GBN, (N_NODES + GBM - 1) / GBM);
        gemm_tf32<<<grid, 256>>>(N_NODES, H2, HIDDEN, o1, W2, h2);
    }

    // 5. z = agg(h2) + b2
    {
        long long threads = (long long)N_NODES * 32;
        k_agg_csr<H2, false><<<(unsigned)((threads + 255) / 256), 256>>>(
            rowptr, csrc, h2, dinv, b2, z);
    }

    // 6. decode
    {
        long long threads = (long long)2 * N_EDGES * 32;
        k_decode<<<(unsigned)((threads + 255) / 256), 256>>>(peR, neR, z, out);
    }
}